// round 1
// baseline (speedup 1.0000x reference)
#include <cuda_runtime.h>

#define FULL 0xFFFFFFFFu

// Problem constants
#define BATCH 32
#define IN    2048
#define OUT   2048
#define KNUM  8
#define HDIM  512

// Scratch (device globals; fully overwritten every call -> graph-replay safe)
__device__ float g_h_partial[32 * HDIM];
__device__ float g_alpha[KNUM];

// ---------------------------------------------------------------------------
// K0a: partial sums of relu-input h = cond @ w1  (each block owns 64 i-rows)
// ---------------------------------------------------------------------------
__global__ void mlp1_kernel(const float* __restrict__ cond,
                            const float* __restrict__ w1) {
    int j  = threadIdx.x;      // 0..511  (H index, coalesced over w1 rows)
    int p  = blockIdx.x;       // 0..31
    int i0 = p * 64;
    float s = 0.f;
#pragma unroll 8
    for (int i = 0; i < 64; ++i) {
        s += cond[i0 + i] * w1[(i0 + i) * HDIM + j];
    }
    g_h_partial[p * HDIM + j] = s;
}

// ---------------------------------------------------------------------------
// K0b: reduce partials, relu, scores = h @ w2 + b2, softmax -> g_alpha
// ---------------------------------------------------------------------------
__global__ void mlp2_kernel(const float* __restrict__ b1,
                            const float* __restrict__ w2,
                            const float* __restrict__ b2) {
    __shared__ float h_s[HDIM];
    __shared__ float s_s[KNUM];
    int j = threadIdx.x;       // 512 threads
    float h = b1[j];
#pragma unroll
    for (int p = 0; p < 32; ++p) h += g_h_partial[p * HDIM + j];
    h_s[j] = fmaxf(h, 0.f);
    __syncthreads();

    int wid = j >> 5, lane = j & 31;
    if (wid < KNUM) {
        float s = 0.f;
#pragma unroll
        for (int m = 0; m < HDIM / 32; ++m) {
            int jj = lane + m * 32;
            s += h_s[jj] * w2[jj * KNUM + wid];
        }
#pragma unroll
        for (int off = 16; off; off >>= 1) s += __shfl_xor_sync(FULL, s, off);
        if (lane == 0) s_s[wid] = s + b2[wid];
    }
    __syncthreads();
    if (j == 0) {
        float mx = -1e30f;
#pragma unroll
        for (int k = 0; k < KNUM; ++k) mx = fmaxf(mx, s_s[k]);
        float e[KNUM];
        float sum = 0.f;
#pragma unroll
        for (int k = 0; k < KNUM; ++k) { e[k] = __expf(s_s[k] - mx); sum += e[k]; }
        float inv = 1.f / sum;
#pragma unroll
        for (int k = 0; k < KNUM; ++k) g_alpha[k] = e[k] * inv;
    }
}

// ---------------------------------------------------------------------------
// Main: out[b,o] = sum_i (sum_k a_k KW[k,o,i]) * x[b,i] + sum_k a_k kb[k,o]
// grid 256 blocks x 256 threads; each warp owns one output column o.
// ---------------------------------------------------------------------------
__global__ __launch_bounds__(256) void main_kernel(
        const float* __restrict__ x,    // [32, 2048]
        const float* __restrict__ kw,   // [8, 2048, 2048]
        const float* __restrict__ kb,   // [8, 2048]
        float* __restrict__ out) {      // [32, 2048]
    __shared__ float x_s[128 * 33];     // [i_local][b], padded row stride 33
    __shared__ float a_s[KNUM];
    __shared__ float out_s[BATCH * 8];  // [b][wid]

    int t    = threadIdx.x;
    int wid  = t >> 5;
    int lane = t & 31;
    int o    = blockIdx.x * 8 + wid;

    if (t < KNUM) a_s[t] = g_alpha[t];

    const float* kwo = kw + (long)o * IN;
    float acc0 = 0.f, acc1 = 0.f;

    for (int i_base = 0; i_base < IN; i_base += 128) {
        __syncthreads();  // protect x_s reuse (also fences a_s on iter 0)
        // stage x tile transposed: x_s[il][b] = x[b][i_base+il]
#pragma unroll
        for (int jj = 0; jj < 16; ++jj) {
            int idx = jj * 256 + t;      // 0..4095
            int b   = idx >> 7;          // /128
            int il  = idx & 127;
            x_s[il * 33 + b] = x[b * IN + i_base + il];
        }
        __syncthreads();

        // aggregate 8 expert slices for this warp's o, 4 i's per lane
        int i = i_base + lane * 4;
        float4 w = make_float4(0.f, 0.f, 0.f, 0.f);
#pragma unroll
        for (int k = 0; k < KNUM; ++k) {
            float4 v = *reinterpret_cast<const float4*>(
                           kwo + (long)k * (IN * OUT) + i);
            float ak = a_s[k];
            w.x += ak * v.x; w.y += ak * v.y;
            w.z += ak * v.z; w.w += ak * v.w;
        }

        // lane <-> b swap: lane is the batch row, broadcast w from src lane
#pragma unroll
        for (int src = 0; src < 32; ++src) {
            float wx = __shfl_sync(FULL, w.x, src);
            float wy = __shfl_sync(FULL, w.y, src);
            float wz = __shfl_sync(FULL, w.z, src);
            float ww = __shfl_sync(FULL, w.w, src);
            const float* xp = &x_s[(src * 4) * 33 + lane];
            acc0 += wx * xp[0];
            acc1 += wy * xp[33];
            acc0 += wz * xp[66];
            acc1 += ww * xp[99];
        }
    }

    // aggregated bias (uniform per warp, redundantly computed per lane)
    float bacc = 0.f;
#pragma unroll
    for (int k = 0; k < KNUM; ++k) bacc += a_s[k] * kb[k * OUT + o];

    float res = acc0 + acc1 + bacc;

    // transpose through smem for 32B-contiguous stores
    __syncthreads();
    out_s[lane * 8 + wid] = res;
    __syncthreads();
    {
        int b  = t >> 3;      // 0..31
        int oi = t & 7;       // 0..7
        out[b * OUT + blockIdx.x * 8 + oi] = out_s[b * 8 + oi];
    }
}

// ---------------------------------------------------------------------------
extern "C" void kernel_launch(void* const* d_in, const int* in_sizes, int n_in,
                              void* d_out, int out_size) {
    const float* x    = (const float*)d_in[0];
    const float* cond = (const float*)d_in[1];
    const float* w1   = (const float*)d_in[2];
    const float* b1   = (const float*)d_in[3];
    const float* w2   = (const float*)d_in[4];
    const float* b2   = (const float*)d_in[5];
    const float* kw   = (const float*)d_in[6];
    const float* kb   = (const float*)d_in[7];
    float* out = (float*)d_out;

    mlp1_kernel<<<32, HDIM>>>(cond, w1);
    mlp2_kernel<<<1, HDIM>>>(b1, w2, b2);
    main_kernel<<<OUT / 8, 256>>>(x, kw, kb, out);
}

// round 2
// speedup vs baseline: 1.2427x; 1.2427x over previous
#include <cuda_runtime.h>

#define FULL 0xFFFFFFFFu

// Problem constants
#define BATCH 32
#define IN    2048
#define OUT   2048
#define KNUM  8
#define HDIM  512
#define KSZ   (IN * OUT)        // elements per expert slice: 4M

#define IBLK  256               // i-range per main block
#define NCHUNK (IN / IBLK)      // 8 i-chunks
#define OBLK  8                 // o's per block (one per warp)
#define NOBLK (OUT / OBLK)      // 256 o-blocks

// Scratch (device globals; fully overwritten every call -> graph-replay safe)
__device__ float g_h_partial[128 * HDIM];
__device__ float g_alpha[KNUM];
__device__ float g_part[NCHUNK * BATCH * OUT];   // 2 MB partial outputs

// ---------------------------------------------------------------------------
// K0a: partial sums of h = cond @ w1 ; 128 blocks, 16 i-rows each
// ---------------------------------------------------------------------------
__global__ void mlp1_kernel(const float* __restrict__ cond,
                            const float* __restrict__ w1) {
    int j  = threadIdx.x;       // 0..511
    int p  = blockIdx.x;        // 0..127
    int i0 = p * 16;
    float s = 0.f;
#pragma unroll
    for (int i = 0; i < 16; ++i)
        s += cond[i0 + i] * w1[(i0 + i) * HDIM + j];
    g_h_partial[p * HDIM + j] = s;
}

// ---------------------------------------------------------------------------
// K0b: reduce partials, relu, scores = h @ w2 + b2, softmax -> g_alpha
// ---------------------------------------------------------------------------
__global__ void mlp2_kernel(const float* __restrict__ b1,
                            const float* __restrict__ w2,
                            const float* __restrict__ b2) {
    __shared__ float h_s[HDIM];
    __shared__ float s_s[KNUM];
    int j = threadIdx.x;        // 512 threads
    float h = b1[j];
#pragma unroll 8
    for (int p = 0; p < 128; ++p) h += g_h_partial[p * HDIM + j];
    h_s[j] = fmaxf(h, 0.f);
    __syncthreads();

    int wid = j >> 5, lane = j & 31;
    if (wid < KNUM) {
        float s = 0.f;
#pragma unroll
        for (int m = 0; m < HDIM / 32; ++m) {
            int jj = lane + m * 32;
            s += h_s[jj] * w2[jj * KNUM + wid];
        }
#pragma unroll
        for (int off = 16; off; off >>= 1) s += __shfl_xor_sync(FULL, s, off);
        if (lane == 0) s_s[wid] = s + b2[wid];
    }
    __syncthreads();
    if (j == 0) {
        float mx = -1e30f;
#pragma unroll
        for (int k = 0; k < KNUM; ++k) mx = fmaxf(mx, s_s[k]);
        float e[KNUM];
        float sum = 0.f;
#pragma unroll
        for (int k = 0; k < KNUM; ++k) { e[k] = __expf(s_s[k] - mx); sum += e[k]; }
        float inv = 1.f / sum;
#pragma unroll
        for (int k = 0; k < KNUM; ++k) g_alpha[k] = e[k] * inv;
    }
}

// ---------------------------------------------------------------------------
// Main: partial[c][b][o] = sum_{i in chunk c} (sum_k a_k KW[k,o,i]) * x[b,i]
// grid = NCHUNK * NOBLK blocks x 256 threads. Warp owns one o; lane owns b.
// Register double-buffered kw loads overlap the shuffle/FMA phase.
// ---------------------------------------------------------------------------
__global__ __launch_bounds__(256) void main_kernel(
        const float* __restrict__ x,    // [32, 2048]
        const float* __restrict__ kw) { // [8, 2048, 2048]
    __shared__ float x_s[IBLK * 33];    // [i_local][b], padded stride 33
    __shared__ float a_s[KNUM];
    __shared__ float out_s[BATCH * 9];  // padded stride 9

    int t    = threadIdx.x;
    int wid  = t >> 5;
    int lane = t & 31;
    int ob   = blockIdx.x & (NOBLK - 1);   // 0..255
    int c    = blockIdx.x >> 8;            // 0..7
    int o    = ob * OBLK + wid;
    int i0   = c * IBLK;

    if (t < KNUM) a_s[t] = g_alpha[t];

    // stage x tile transposed: x_s[il][b] = x[b][i0+il]
    // idx: il = idx & 255 (coalesced global), b = idx >> 8
#pragma unroll
    for (int jj = 0; jj < (IBLK * BATCH) / 256; ++jj) {
        int idx = jj * 256 + t;
        int b   = idx >> 8;
        int il  = idx & (IBLK - 1);
        x_s[il * 33 + b] = x[b * IN + i0 + il];
    }
    __syncthreads();

    const float* kwo = kw + (size_t)o * IN + i0 + lane * 4;

    float4 cur[KNUM];
#pragma unroll
    for (int k = 0; k < KNUM; ++k)
        cur[k] = *reinterpret_cast<const float4*>(kwo + (size_t)k * KSZ);

    float acc0 = 0.f, acc1 = 0.f;

#pragma unroll
    for (int tile = 0; tile < IBLK / 128; ++tile) {
        float4 nxt[KNUM];
        if (tile < IBLK / 128 - 1) {
#pragma unroll
            for (int k = 0; k < KNUM; ++k)
                nxt[k] = *reinterpret_cast<const float4*>(
                             kwo + (size_t)k * KSZ + (tile + 1) * 128);
        }

        // aggregate experts for this warp's o (4 i's per lane)
        float4 w = make_float4(0.f, 0.f, 0.f, 0.f);
#pragma unroll
        for (int k = 0; k < KNUM; ++k) {
            float ak = a_s[k];
            w.x += ak * cur[k].x; w.y += ak * cur[k].y;
            w.z += ak * cur[k].z; w.w += ak * cur[k].w;
        }

        // lane <-> b role swap: lane is the batch row
#pragma unroll
        for (int src = 0; src < 32; ++src) {
            float wx = __shfl_sync(FULL, w.x, src);
            float wy = __shfl_sync(FULL, w.y, src);
            float wz = __shfl_sync(FULL, w.z, src);
            float ww = __shfl_sync(FULL, w.w, src);
            const float* xp = &x_s[(tile * 128 + src * 4) * 33 + lane];
            acc0 += wx * xp[0];
            acc1 += wy * xp[33];
            acc0 += wz * xp[66];
            acc1 += ww * xp[99];
        }

#pragma unroll
        for (int k = 0; k < KNUM; ++k) cur[k] = nxt[k];
    }

    // transpose through smem for contiguous partial stores
    __syncthreads();
    out_s[lane * 9 + wid] = acc0 + acc1;
    __syncthreads();
    {
        int b  = t >> 3;       // 0..31
        int oi = t & 7;        // 0..7
        g_part[(size_t)c * (BATCH * OUT) + b * OUT + ob * OBLK + oi] =
            out_s[b * 9 + oi];
    }
}

// ---------------------------------------------------------------------------
// Reduce: out[b,o] = sum_c g_part[c][b][o] + sum_k a_k kb[k,o]
// ---------------------------------------------------------------------------
__global__ __launch_bounds__(256) void reduce_kernel(
        const float* __restrict__ kb, float* __restrict__ out) {
    __shared__ float a_s[KNUM];
    if (threadIdx.x < KNUM) a_s[threadIdx.x] = g_alpha[threadIdx.x];
    __syncthreads();
    int e = blockIdx.x * 256 + threadIdx.x;   // 0..65535
    int o = e & (OUT - 1);
    float s = 0.f;
#pragma unroll
    for (int c = 0; c < NCHUNK; ++c) s += g_part[c * (BATCH * OUT) + e];
    float bacc = 0.f;
#pragma unroll
    for (int k = 0; k < KNUM; ++k) bacc += a_s[k] * kb[k * OUT + o];
    out[e] = s + bacc;
}

// ---------------------------------------------------------------------------
extern "C" void kernel_launch(void* const* d_in, const int* in_sizes, int n_in,
                              void* d_out, int out_size) {
    const float* x    = (const float*)d_in[0];
    const float* cond = (const float*)d_in[1];
    const float* w1   = (const float*)d_in[2];
    const float* b1   = (const float*)d_in[3];
    const float* w2   = (const float*)d_in[4];
    const float* b2   = (const float*)d_in[5];
    const float* kw   = (const float*)d_in[6];
    const float* kb   = (const float*)d_in[7];
    float* out = (float*)d_out;

    mlp1_kernel<<<128, HDIM>>>(cond, w1);
    mlp2_kernel<<<1, HDIM>>>(b1, w2, b2);
    main_kernel<<<NCHUNK * NOBLK, 256>>>(x, kw);
    reduce_kernel<<<(BATCH * OUT) / 256, 256>>>(kb, out);
}

// round 3
// speedup vs baseline: 1.6215x; 1.3048x over previous
#include <cuda_runtime.h>

#define FULL 0xFFFFFFFFu

// Problem constants
#define BATCH 32
#define IN    2048
#define OUT   2048
#define KNUM  8
#define HDIM  512
#define KSZ   (IN * OUT)          // elements per expert slice: 4M

#define IBLK   256                // i-range per main block
#define NCHUNK (IN / IBLK)        // 8 i-chunks
#define OBLK   16                 // o's per block (2 per warp)
#define NOBLK  (OUT / OBLK)       // 128 o-blocks
#define XSTR   260                // x_s row stride (260 % 32 == 4 -> LDS.128 conflict-free)

// Scratch (device globals; fully overwritten every call -> graph-replay safe)
__device__ float g_h_partial[128 * HDIM];
__device__ float g_alpha[KNUM];
__device__ float g_part[NCHUNK * BATCH * OUT];   // 2 MB partial outputs

// ---------------------------------------------------------------------------
// K0a: partial sums of h = cond @ w1 ; 128 blocks, 16 i-rows each
// ---------------------------------------------------------------------------
__global__ void mlp1_kernel(const float* __restrict__ cond,
                            const float* __restrict__ w1) {
    int j  = threadIdx.x;         // 0..511
    int p  = blockIdx.x;          // 0..127
    int i0 = p * 16;
    float s = 0.f;
#pragma unroll
    for (int i = 0; i < 16; ++i)
        s += cond[i0 + i] * w1[(i0 + i) * HDIM + j];
    g_h_partial[p * HDIM + j] = s;
}

// ---------------------------------------------------------------------------
// K0b: reduce partials, relu, scores = h @ w2 + b2, softmax -> g_alpha
// ---------------------------------------------------------------------------
__global__ void mlp2_kernel(const float* __restrict__ b1,
                            const float* __restrict__ w2,
                            const float* __restrict__ b2) {
    __shared__ float h_s[HDIM];
    __shared__ float s_s[KNUM];
    int j = threadIdx.x;          // 512 threads
    float h = b1[j];
#pragma unroll 8
    for (int p = 0; p < 128; ++p) h += g_h_partial[p * HDIM + j];
    h_s[j] = fmaxf(h, 0.f);
    __syncthreads();

    int wid = j >> 5, lane = j & 31;
    if (wid < KNUM) {
        float s = 0.f;
#pragma unroll
        for (int m = 0; m < HDIM / 32; ++m) {
            int jj = lane + m * 32;
            s += h_s[jj] * w2[jj * KNUM + wid];
        }
#pragma unroll
        for (int off = 16; off; off >>= 1) s += __shfl_xor_sync(FULL, s, off);
        if (lane == 0) s_s[wid] = s + b2[wid];
    }
    __syncthreads();
    if (j == 0) {
        float mx = -1e30f;
#pragma unroll
        for (int k = 0; k < KNUM; ++k) mx = fmaxf(mx, s_s[k]);
        float e[KNUM];
        float sum = 0.f;
#pragma unroll
        for (int k = 0; k < KNUM; ++k) { e[k] = __expf(s_s[k] - mx); sum += e[k]; }
        float inv = 1.f / sum;
#pragma unroll
        for (int k = 0; k < KNUM; ++k) g_alpha[k] = e[k] * inv;
    }
}

// ---------------------------------------------------------------------------
// Main: partial[c][b][o] = sum_{i in chunk c} (sum_k a_k KW[k,o,i]) * x[b,i]
// grid = NCHUNK*NOBLK = 1024 blocks x 256 threads.
// Warp owns o0 = ob*16+wid and o1 = o0+8; lane = batch row b.
// Per 128-i half: warp aggregates experts in regs, stages via one STS.128
// into warp-private smem, compute loop reads broadcast LDS.128 + x LDS.128.
// ---------------------------------------------------------------------------
__global__ __launch_bounds__(256, 2) void main_kernel(
        const float* __restrict__ x,    // [32, 2048]
        const float* __restrict__ kw) { // [8, 2048, 2048]
    __shared__ float x_s[BATCH * XSTR];          // [b][il], stride 260
    __shared__ float w_s[8][2][128];             // [warp][o-half][il]
    __shared__ float a_s[KNUM];
    __shared__ float out_s[BATCH][OBLK + 1];     // stride 17

    int t    = threadIdx.x;
    int wid  = t >> 5;
    int lane = t & 31;
    int ob   = blockIdx.x & (NOBLK - 1);         // 0..127
    int c    = blockIdx.x >> 7;                  // 0..7
    int o0   = ob * OBLK + wid;
    int o1   = o0 + 8;
    int i0   = c * IBLK;

    if (t < KNUM) a_s[t] = g_alpha[t];

    // stage x tile: x_s[b][il] = x[b][i0+il], vectorized (float4)
    const float4* x4 = reinterpret_cast<const float4*>(x);
#pragma unroll
    for (int jj = 0; jj < (IBLK * BATCH) / (4 * 256); ++jj) {
        int idx = jj * 256 + t;                  // 0..2047 (float4 units)
        int b   = idx >> 6;                      // 64 float4 per row
        int il4 = idx & 63;
        *reinterpret_cast<float4*>(&x_s[b * XSTR + il4 * 4]) =
            x4[(b * IN + i0) / 4 + il4];
    }
    __syncthreads();

    float a[KNUM];
#pragma unroll
    for (int k = 0; k < KNUM; ++k) a[k] = a_s[k];

    const float* base0 = kw + (size_t)o0 * IN + i0 + lane * 4;
    const float* base1 = kw + (size_t)o1 * IN + i0 + lane * 4;

    float4 cur0[KNUM], cur1[KNUM];
#pragma unroll
    for (int k = 0; k < KNUM; ++k) {
        cur0[k] = *reinterpret_cast<const float4*>(base0 + (size_t)k * KSZ);
        cur1[k] = *reinterpret_cast<const float4*>(base1 + (size_t)k * KSZ);
    }

    float acc0[4] = {0.f, 0.f, 0.f, 0.f};
    float acc1[4] = {0.f, 0.f, 0.f, 0.f};

#pragma unroll
    for (int h = 0; h < 2; ++h) {
        // aggregate experts for this warp's two o's (consumes cur)
        float4 w40 = make_float4(0.f, 0.f, 0.f, 0.f);
        float4 w41 = make_float4(0.f, 0.f, 0.f, 0.f);
#pragma unroll
        for (int k = 0; k < KNUM; ++k) {
            float ak = a[k];
            w40.x += ak * cur0[k].x; w40.y += ak * cur0[k].y;
            w40.z += ak * cur0[k].z; w40.w += ak * cur0[k].w;
            w41.x += ak * cur1[k].x; w41.y += ak * cur1[k].y;
            w41.z += ak * cur1[k].z; w41.w += ak * cur1[k].w;
        }

        // prefetch next half while computing this one
        if (h == 0) {
#pragma unroll
            for (int k = 0; k < KNUM; ++k) {
                cur0[k] = *reinterpret_cast<const float4*>(
                              base0 + (size_t)k * KSZ + 128);
                cur1[k] = *reinterpret_cast<const float4*>(
                              base1 + (size_t)k * KSZ + 128);
            }
        }

        // stage aggregated strip (warp-private)
        *reinterpret_cast<float4*>(&w_s[wid][0][lane * 4]) = w40;
        *reinterpret_cast<float4*>(&w_s[wid][1][lane * 4]) = w41;
        __syncwarp();

        // compute: lane = b; 4 i per step; broadcast w, vector x
#pragma unroll 8
        for (int src = 0; src < 32; ++src) {
            float4 xq  = *reinterpret_cast<const float4*>(
                             &x_s[lane * XSTR + h * 128 + src * 4]);
            float4 wq0 = *reinterpret_cast<const float4*>(&w_s[wid][0][src * 4]);
            float4 wq1 = *reinterpret_cast<const float4*>(&w_s[wid][1][src * 4]);
            acc0[0] += wq0.x * xq.x; acc0[1] += wq0.y * xq.y;
            acc0[2] += wq0.z * xq.z; acc0[3] += wq0.w * xq.w;
            acc1[0] += wq1.x * xq.x; acc1[1] += wq1.y * xq.y;
            acc1[2] += wq1.z * xq.z; acc1[3] += wq1.w * xq.w;
        }
        __syncwarp();   // before w_s overwrite next half
    }

    float v0 = (acc0[0] + acc0[1]) + (acc0[2] + acc0[3]);
    float v1 = (acc1[0] + acc1[1]) + (acc1[2] + acc1[3]);

    // transpose through smem for contiguous partial stores
    __syncthreads();
    out_s[lane][wid]     = v0;
    out_s[lane][wid + 8] = v1;
    __syncthreads();
#pragma unroll
    for (int r = 0; r < 2; ++r) {
        int idx = r * 256 + t;                   // 0..511
        int b   = idx >> 4;
        int oi  = idx & 15;
        g_part[(size_t)c * (BATCH * OUT) + b * OUT + ob * OBLK + oi] =
            out_s[b][oi];
    }
}

// ---------------------------------------------------------------------------
// Reduce: out[b,o] = sum_c g_part[c][b][o] + sum_k a_k kb[k,o]   (float4)
// ---------------------------------------------------------------------------
__global__ __launch_bounds__(256) void reduce_kernel(
        const float* __restrict__ kb, float* __restrict__ out) {
    __shared__ float a_s[KNUM];
    if (threadIdx.x < KNUM) a_s[threadIdx.x] = g_alpha[threadIdx.x];
    __syncthreads();

    int e4 = blockIdx.x * 256 + threadIdx.x;     // 0..16383 (float4 units)
    const float4* part4 = reinterpret_cast<const float4*>(g_part);
    const float4* kb4   = reinterpret_cast<const float4*>(kb);

    float4 s = make_float4(0.f, 0.f, 0.f, 0.f);
#pragma unroll
    for (int c = 0; c < NCHUNK; ++c) {
        float4 v = part4[c * (BATCH * OUT / 4) + e4];
        s.x += v.x; s.y += v.y; s.z += v.z; s.w += v.w;
    }

    int o4 = e4 & (OUT / 4 - 1);                 // 0..511
#pragma unroll
    for (int k = 0; k < KNUM; ++k) {
        float4 bv = kb4[k * (OUT / 4) + o4];
        float ak = a_s[k];
        s.x += ak * bv.x; s.y += ak * bv.y;
        s.z += ak * bv.z; s.w += ak * bv.w;
    }
    reinterpret_cast<float4*>(out)[e4] = s;
}

// ---------------------------------------------------------------------------
extern "C" void kernel_launch(void* const* d_in, const int* in_sizes, int n_in,
                              void* d_out, int out_size) {
    const float* x    = (const float*)d_in[0];
    const float* cond = (const float*)d_in[1];
    const float* w1   = (const float*)d_in[2];
    const float* b1   = (const float*)d_in[3];
    const float* w2   = (const float*)d_in[4];
    const float* b2   = (const float*)d_in[5];
    const float* kw   = (const float*)d_in[6];
    const float* kb   = (const float*)d_in[7];
    float* out = (float*)d_out;

    mlp1_kernel<<<128, HDIM>>>(cond, w1);
    mlp2_kernel<<<1, HDIM>>>(b1, w2, b2);
    main_kernel<<<NCHUNK * NOBLK, 256>>>(x, kw);
    reduce_kernel<<<(BATCH * OUT) / (4 * 256), 256>>>(kb, out);
}